// round 1
// baseline (speedup 1.0000x reference)
#include <cuda_runtime.h>
#include <math.h>

#define NB 4
#define SS 2048
#define TD 768
#define HID 512
#define NH 8
#define HD 64
#define VD 768
#define MM (NB*SS)   // 8192

// Scratch (static device globals; allocation-free per harness rules)
__device__ float g_Q[NB*NH*SS*HD];   // [bh][s][d]
__device__ float g_K[NB*NH*SS*HD];
__device__ float g_V[NB*NH*SS*HD];
__device__ float g_A[MM*HID];        // attended, [b*s][h*d]

// ---------------------------------------------------------------------------
// Kernel 1: fused QKV projection. Y = X @ W + b, written as [b,h,s,d].
// Tiles: BM=128, BN=64, BK=32. 256 threads, each computes 8x4 outputs.
// X tile stored transposed [k][m] with XOR swizzle (conflict-free).
// ---------------------------------------------------------------------------
__global__ __launch_bounds__(256) void qkv_kernel(
    const float* __restrict__ X,
    const float* __restrict__ Wq, const float* __restrict__ bq,
    const float* __restrict__ Wk, const float* __restrict__ bk,
    const float* __restrict__ Wv, const float* __restrict__ bv)
{
    __shared__ float4 Xs4[32*32];   // [k][m-group], 32 f4-groups = 128 floats per k
    __shared__ float4 Ws4[32*16];   // [k][n-group]

    const int z = blockIdx.z;
    const float* W    = (z == 0) ? Wq : (z == 1) ? Wk : Wv;
    const float* bias = (z == 0) ? bq : (z == 1) ? bk : bv;
    float* out        = (z == 0) ? g_Q : (z == 1) ? g_K : g_V;

    const int t  = threadIdx.x;
    const int ty = t >> 4;          // 0..15  -> rows ty*8 .. ty*8+7
    const int tx = t & 15;          // 0..15  -> cols tx*4 .. tx*4+3
    const int m0 = blockIdx.y * 128;
    const int n0 = blockIdx.x * 64;

    float acc[8][4];
#pragma unroll
    for (int i = 0; i < 8; i++)
#pragma unroll
        for (int j = 0; j < 4; j++) acc[i][j] = 0.f;

    float* Xs = (float*)Xs4;

    for (int kt = 0; kt < TD; kt += 32) {
        // Load X tile (128x32) transposed+swizzled into Xs
#pragma unroll
        for (int it = 0; it < 4; it++) {
            int idx = t + it * 256;
            int row = idx >> 3;          // 0..127
            int fc  = idx & 7;           // f4 column within BK (k>>2)
            float4 v = *(const float4*)&X[(m0 + row) * TD + kt + fc * 4];
            int rsw = row ^ (fc << 2);   // swizzle bits 2..4 of row
            Xs[(fc*4 + 0) * 128 + rsw] = v.x;
            Xs[(fc*4 + 1) * 128 + rsw] = v.y;
            Xs[(fc*4 + 2) * 128 + rsw] = v.z;
            Xs[(fc*4 + 3) * 128 + rsw] = v.w;
        }
        // Load W tile (32x64)
#pragma unroll
        for (int it = 0; it < 2; it++) {
            int idx = t + it * 256;
            int kr = idx >> 4;           // 0..31
            int fc = idx & 15;
            Ws4[kr * 16 + fc] = *(const float4*)&W[(kt + kr) * HID + n0 + fc * 4];
        }
        __syncthreads();

#pragma unroll 8
        for (int k = 0; k < 32; k++) {
            int sw = k >> 2;
            float4 a0 = Xs4[k * 32 + ((ty * 2)     ^ sw)];
            float4 a1 = Xs4[k * 32 + ((ty * 2 + 1) ^ sw)];
            float4 bv4 = Ws4[k * 16 + tx];
            float a[8] = {a0.x, a0.y, a0.z, a0.w, a1.x, a1.y, a1.z, a1.w};
            float bb[4] = {bv4.x, bv4.y, bv4.z, bv4.w};
#pragma unroll
            for (int i = 0; i < 8; i++)
#pragma unroll
                for (int j = 0; j < 4; j++) acc[i][j] += a[i] * bb[j];
        }
        __syncthreads();
    }

    // Bias + store to [b,h,s,d]
    float4 bb = *(const float4*)&bias[n0 + tx * 4];
    const int h = n0 >> 6;   // = blockIdx.x (BN=64 == head_dim)
#pragma unroll
    for (int i = 0; i < 8; i++) {
        int m  = m0 + ty * 8 + i;
        int bq_ = m >> 11;        // / 2048
        int s   = m & 2047;
        float4 o = make_float4(acc[i][0] + bb.x, acc[i][1] + bb.y,
                               acc[i][2] + bb.z, acc[i][3] + bb.w);
        *(float4*)&out[(((size_t)(bq_ * NH + h) * SS + s) << 6) + tx * 4] = o;
    }
}

// ---------------------------------------------------------------------------
// Kernel 2: flash attention (online softmax). One CTA per (bh, 64-row q tile).
// Q,K stored d-major in smem with group-XOR swizzle -> conflict-free f4 loads.
// ---------------------------------------------------------------------------
__global__ __launch_bounds__(256) void attn_kernel()
{
    extern __shared__ float4 sm4[];
    float4* Qst = sm4;            // [d][cgroup] 64x16 f4 (transposed, swizzled)
    float4* Kst = sm4 + 1024;
    float4* Vs  = sm4 + 2048;     // [k][cgroup] row-major
    float4* Ps  = sm4 + 3072;     // [r][cgroup] row-major scores/probs
    float*  rowc = (float*)(sm4 + 4096);   // 64 floats

    const int t  = threadIdx.x;
    const int ty = t >> 4;
    const int tx = t & 15;
    const int bh = blockIdx.y;
    const int qt = blockIdx.x;

    const float* Qg = g_Q + (size_t)bh * SS * HD;
    const float* Kg = g_K + (size_t)bh * SS * HD;
    const float* Vg = g_V + (size_t)bh * SS * HD;

    // Load Q tile transposed + swizzled
    float* Qe = (float*)Qst;
#pragma unroll
    for (int it = 0; it < 4; it++) {
        int idx = t + it * 256;
        int r  = idx >> 4;       // 0..63
        int fd = idx & 15;       // d>>2
        float4 v = *(const float4*)&Qg[(qt * 64 + r) * 64 + fd * 4];
        int csw = r ^ (fd << 2);
        Qe[(fd*4 + 0) * 64 + csw] = v.x;
        Qe[(fd*4 + 1) * 64 + csw] = v.y;
        Qe[(fd*4 + 2) * 64 + csw] = v.z;
        Qe[(fd*4 + 3) * 64 + csw] = v.w;
    }

    float m_run = -INFINITY;   // valid for t < 64 (row owner)
    float l_run = 0.f;
    float O[4][4];
#pragma unroll
    for (int i = 0; i < 4; i++)
#pragma unroll
        for (int j = 0; j < 4; j++) O[i][j] = 0.f;

    float* Ke = (float*)Kst;

    for (int kt = 0; kt < 32; kt++) {
        // Load K (transposed+swizzled) and V (row-major) tiles
#pragma unroll
        for (int it = 0; it < 4; it++) {
            int idx = t + it * 256;
            int r  = idx >> 4;
            int fd = idx & 15;
            const float* src = &Kg[(kt * 64 + r) * 64 + fd * 4];
            float4 kv = *(const float4*)src;
            int csw = r ^ (fd << 2);
            Ke[(fd*4 + 0) * 64 + csw] = kv.x;
            Ke[(fd*4 + 1) * 64 + csw] = kv.y;
            Ke[(fd*4 + 2) * 64 + csw] = kv.z;
            Ke[(fd*4 + 3) * 64 + csw] = kv.w;
            Vs[r * 16 + fd] = *(const float4*)&Vg[(kt * 64 + r) * 64 + fd * 4];
        }
        __syncthreads();

        // S = Q K^T (each thread 4x4)
        float s_acc[4][4];
#pragma unroll
        for (int i = 0; i < 4; i++)
#pragma unroll
            for (int j = 0; j < 4; j++) s_acc[i][j] = 0.f;

#pragma unroll 8
        for (int d = 0; d < 64; d++) {
            int sw = d >> 2;
            float4 qa = Qst[d * 16 + (ty ^ sw)];
            float4 kb = Kst[d * 16 + (tx ^ sw)];
            float a[4] = {qa.x, qa.y, qa.z, qa.w};
            float b[4] = {kb.x, kb.y, kb.z, kb.w};
#pragma unroll
            for (int i = 0; i < 4; i++)
#pragma unroll
                for (int j = 0; j < 4; j++) s_acc[i][j] += a[i] * b[j];
        }
        // write scaled scores
#pragma unroll
        for (int i = 0; i < 4; i++)
            Ps[(ty * 4 + i) * 16 + tx] =
                make_float4(s_acc[i][0] * 0.125f, s_acc[i][1] * 0.125f,
                            s_acc[i][2] * 0.125f, s_acc[i][3] * 0.125f);
        __syncthreads();

        // Online softmax: one thread per row
        if (t < 64) {
            float* pr = (float*)Ps + t * 64;
            float mx = m_run;
#pragma unroll 8
            for (int k = 0; k < 64; k++) mx = fmaxf(mx, pr[k]);
            float corr = __expf(m_run - mx);
            float ls = 0.f;
#pragma unroll 8
            for (int k = 0; k < 64; k++) {
                float e = __expf(pr[k] - mx);
                pr[k] = e;
                ls += e;
            }
            l_run = l_run * corr + ls;
            m_run = mx;
            rowc[t] = corr;
        }
        __syncthreads();

        // rescale O, then O += P V
        float cr[4];
#pragma unroll
        for (int i = 0; i < 4; i++) cr[i] = rowc[ty * 4 + i];
#pragma unroll
        for (int i = 0; i < 4; i++)
#pragma unroll
            for (int j = 0; j < 4; j++) O[i][j] *= cr[i];

#pragma unroll 4
        for (int kq = 0; kq < 16; kq++) {
            float4 p[4];
#pragma unroll
            for (int i = 0; i < 4; i++) p[i] = Ps[(ty * 4 + i) * 16 + kq];
            float4 v0 = Vs[(kq * 4 + 0) * 16 + tx];
            float4 v1 = Vs[(kq * 4 + 1) * 16 + tx];
            float4 v2 = Vs[(kq * 4 + 2) * 16 + tx];
            float4 v3 = Vs[(kq * 4 + 3) * 16 + tx];
#pragma unroll
            for (int i = 0; i < 4; i++) {
                O[i][0] += p[i].x * v0.x + p[i].y * v1.x + p[i].z * v2.x + p[i].w * v3.x;
                O[i][1] += p[i].x * v0.y + p[i].y * v1.y + p[i].z * v2.y + p[i].w * v3.y;
                O[i][2] += p[i].x * v0.z + p[i].y * v1.z + p[i].z * v2.z + p[i].w * v3.z;
                O[i][3] += p[i].x * v0.w + p[i].y * v1.w + p[i].z * v2.w + p[i].w * v3.w;
            }
        }
        __syncthreads();
    }

    if (t < 64) rowc[t] = 1.f / l_run;
    __syncthreads();

    const int b_ = bh >> 3, h = bh & 7;
#pragma unroll
    for (int i = 0; i < 4; i++) {
        int r = ty * 4 + i;
        float inv = rowc[r];
        int s_ = qt * 64 + r;
        float4 o = make_float4(O[i][0] * inv, O[i][1] * inv,
                               O[i][2] * inv, O[i][3] * inv);
        *(float4*)&g_A[((size_t)(b_ * SS + s_)) * HID + h * 64 + tx * 4] = o;
    }
}

// ---------------------------------------------------------------------------
// Kernel 3: output projection. out = A @ Wo + bo, [8192,512]x[512,768].
// ---------------------------------------------------------------------------
__global__ __launch_bounds__(256) void oproj_kernel(
    const float* __restrict__ Wo, const float* __restrict__ bo,
    float* __restrict__ out)
{
    __shared__ float4 Xs4[32*32];
    __shared__ float4 Ws4[32*16];

    const int t  = threadIdx.x;
    const int ty = t >> 4;
    const int tx = t & 15;
    const int m0 = blockIdx.y * 128;
    const int n0 = blockIdx.x * 64;

    float acc[8][4];
#pragma unroll
    for (int i = 0; i < 8; i++)
#pragma unroll
        for (int j = 0; j < 4; j++) acc[i][j] = 0.f;

    float* Xs = (float*)Xs4;

    for (int kt = 0; kt < HID; kt += 32) {
#pragma unroll
        for (int it = 0; it < 4; it++) {
            int idx = t + it * 256;
            int row = idx >> 3;
            int fc  = idx & 7;
            float4 v = *(const float4*)&g_A[(size_t)(m0 + row) * HID + kt + fc * 4];
            int rsw = row ^ (fc << 2);
            Xs[(fc*4 + 0) * 128 + rsw] = v.x;
            Xs[(fc*4 + 1) * 128 + rsw] = v.y;
            Xs[(fc*4 + 2) * 128 + rsw] = v.z;
            Xs[(fc*4 + 3) * 128 + rsw] = v.w;
        }
#pragma unroll
        for (int it = 0; it < 2; it++) {
            int idx = t + it * 256;
            int kr = idx >> 4;
            int fc = idx & 15;
            Ws4[kr * 16 + fc] = *(const float4*)&Wo[(kt + kr) * VD + n0 + fc * 4];
        }
        __syncthreads();

#pragma unroll 8
        for (int k = 0; k < 32; k++) {
            int sw = k >> 2;
            float4 a0 = Xs4[k * 32 + ((ty * 2)     ^ sw)];
            float4 a1 = Xs4[k * 32 + ((ty * 2 + 1) ^ sw)];
            float4 bv4 = Ws4[k * 16 + tx];
            float a[8] = {a0.x, a0.y, a0.z, a0.w, a1.x, a1.y, a1.z, a1.w};
            float bb[4] = {bv4.x, bv4.y, bv4.z, bv4.w};
#pragma unroll
            for (int i = 0; i < 8; i++)
#pragma unroll
                for (int j = 0; j < 4; j++) acc[i][j] += a[i] * bb[j];
        }
        __syncthreads();
    }

    float4 bb = *(const float4*)&bo[n0 + tx * 4];
#pragma unroll
    for (int i = 0; i < 8; i++) {
        int m = m0 + ty * 8 + i;
        float4 o = make_float4(acc[i][0] + bb.x, acc[i][1] + bb.y,
                               acc[i][2] + bb.z, acc[i][3] + bb.w);
        *(float4*)&out[(size_t)m * VD + n0 + tx * 4] = o;
    }
}

// ---------------------------------------------------------------------------
extern "C" void kernel_launch(void* const* d_in, const int* in_sizes, int n_in,
                              void* d_out, int out_size)
{
    const float* X  = (const float*)d_in[0];
    const float* Wq = (const float*)d_in[1];
    const float* bq = (const float*)d_in[2];
    const float* Wk = (const float*)d_in[3];
    const float* bk = (const float*)d_in[4];
    const float* Wv = (const float*)d_in[5];
    const float* bv = (const float*)d_in[6];
    const float* Wo = (const float*)d_in[7];
    const float* bo = (const float*)d_in[8];
    float* out = (float*)d_out;

    const int attn_smem = 4096 * 16 + 64 * 4;   // 65792 bytes
    cudaFuncSetAttribute(attn_kernel,
                         cudaFuncAttributeMaxDynamicSharedMemorySize, attn_smem);

    qkv_kernel<<<dim3(HID/64, MM/128, 3), 256>>>(X, Wq, bq, Wk, bk, Wv, bv);
    attn_kernel<<<dim3(SS/64, NB*NH), 256, attn_smem>>>();
    oproj_kernel<<<dim3(VD/64, MM/128), 256>>>(Wo, bo, out);
}

// round 4
// speedup vs baseline: 3.1857x; 3.1857x over previous
#include <cuda_runtime.h>
#include <math.h>
#include <cstdint>

#define NB 4
#define SS 2048
#define TD 768
#define HID 512
#define NH 8
#define HD 64
#define VD 768
#define MM (NB*SS)   // 8192

// Scratch
__device__ float g_Q[NB*NH*SS*HD];   // [bh][s][d]
__device__ float g_K[NB*NH*SS*HD];
__device__ float g_V[NB*NH*SS*HD];
__device__ float g_A[MM*HID];        // attended, [b*s][h*d]

// ---------------------------------------------------------------------------
// tf32 helpers (all portable PTX, valid on plain sm_103 target)
// ---------------------------------------------------------------------------
__device__ __forceinline__ float tf32r(float x) {
    uint32_t u;
    asm("cvt.rna.tf32.f32 %0, %1;" : "=r"(u) : "f"(x));
    return __uint_as_float(u);
}
__device__ __forceinline__ float4 tf32r4(float4 v) {
    v.x = tf32r(v.x); v.y = tf32r(v.y); v.z = tf32r(v.z); v.w = tf32r(v.w);
    return v;
}

// m16n8k8 tf32 MMA. Fragment layout (g=lane>>2, tig=lane&3):
//  A: a0=[g][tig] a1=[g+8][tig] a2=[g][tig+4] a3=[g+8][tig+4]
//  B: b0=[k=tig][n=g] b1=[k=tig+4][n=g]
//  C: c0=[g][2tig] c1=[g][2tig+1] c2=[g+8][2tig] c3=[g+8][2tig+1]
__device__ __forceinline__ void mma8(float* c, const uint32_t* a, const uint32_t* b) {
    asm volatile(
        "mma.sync.aligned.m16n8k8.row.col.f32.tf32.tf32.f32 "
        "{%0,%1,%2,%3}, {%4,%5,%6,%7}, {%8,%9}, {%0,%1,%2,%3};"
        : "+f"(c[0]), "+f"(c[1]), "+f"(c[2]), "+f"(c[3])
        : "r"(a[0]), "r"(a[1]), "r"(a[2]), "r"(a[3]), "r"(b[0]), "r"(b[1]));
}

// ===========================================================================
// Projection GEMM body. CTA tile 128(M) x 64(N), BK=32, 128 threads (4 warps),
// warp tile 64x32 (4x4 m16n8k8 tiles).
// Xs padded to 36 floats/row (A-frag LDS banks = 4g+tig: conflict-free).
// Ws padded to 72 floats/row (B-frag LDS banks = 8*tig+g: conflict-free).
// ===========================================================================
__device__ __forceinline__ void proj_body(
    float* Xs, float* Ws,
    const float* __restrict__ A, int lda,
    const float* __restrict__ W, int ldw,
    int kdim, int m0, int n0, float acc[4][4][4])
{
    const int t = threadIdx.x;
    const int w = t >> 5, lane = t & 31, g = lane >> 2, tig = lane & 3;
    const int mw = (w >> 1) * 64, nw = (w & 1) * 32;

#pragma unroll
    for (int mi = 0; mi < 4; mi++)
#pragma unroll
        for (int nj = 0; nj < 4; nj++)
#pragma unroll
            for (int r = 0; r < 4; r++) acc[mi][nj][r] = 0.f;

    for (int kt = 0; kt < kdim; kt += 32) {
        // X chunk [128][32] -> Xs (tf32-rounded)
#pragma unroll
        for (int it = 0; it < 8; it++) {
            int i = t + it * 128;
            int r = i >> 3, fg = i & 7;
            float4 v = tf32r4(*(const float4*)&A[(size_t)(m0 + r) * lda + kt + fg * 4]);
            *(float4*)&Xs[r * 36 + fg * 4] = v;
        }
        // W chunk [32][64] -> Ws
#pragma unroll
        for (int it = 0; it < 4; it++) {
            int i = t + it * 128;
            int r = i >> 4, fg = i & 15;
            float4 v = tf32r4(*(const float4*)&W[(size_t)(kt + r) * ldw + n0 + fg * 4]);
            *(float4*)&Ws[r * 72 + fg * 4] = v;
        }
        __syncthreads();

#pragma unroll
        for (int ks = 0; ks < 4; ks++) {
            uint32_t af[4][4], bf[4][2];
#pragma unroll
            for (int mi = 0; mi < 4; mi++) {
                int r0 = mw + 16 * mi + g;
                af[mi][0] = __float_as_uint(Xs[r0 * 36 + ks * 8 + tig]);
                af[mi][1] = __float_as_uint(Xs[(r0 + 8) * 36 + ks * 8 + tig]);
                af[mi][2] = __float_as_uint(Xs[r0 * 36 + ks * 8 + tig + 4]);
                af[mi][3] = __float_as_uint(Xs[(r0 + 8) * 36 + ks * 8 + tig + 4]);
            }
#pragma unroll
            for (int nj = 0; nj < 4; nj++) {
                bf[nj][0] = __float_as_uint(Ws[(ks * 8 + tig) * 72 + nw + nj * 8 + g]);
                bf[nj][1] = __float_as_uint(Ws[(ks * 8 + tig + 4) * 72 + nw + nj * 8 + g]);
            }
#pragma unroll
            for (int mi = 0; mi < 4; mi++)
#pragma unroll
                for (int nj = 0; nj < 4; nj++)
                    mma8(acc[mi][nj], af[mi], bf[nj]);
        }
        __syncthreads();
    }
}

// ---------------------------------------------------------------------------
// Kernel 1: fused QKV projection -> [bh][s][d]
// ---------------------------------------------------------------------------
__global__ __launch_bounds__(128) void qkv_mma(
    const float* __restrict__ X,
    const float* __restrict__ Wq, const float* __restrict__ bq,
    const float* __restrict__ Wk, const float* __restrict__ bk,
    const float* __restrict__ Wv, const float* __restrict__ bv)
{
    __shared__ float Xs[128 * 36];
    __shared__ float Ws[32 * 72];

    const int z = blockIdx.z;
    const float* W    = (z == 0) ? Wq : (z == 1) ? Wk : Wv;
    const float* bias = (z == 0) ? bq : (z == 1) ? bk : bv;
    float* out        = (z == 0) ? g_Q : (z == 1) ? g_K : g_V;

    const int m0 = blockIdx.y * 128;
    const int n0 = blockIdx.x * 64;
    const int h  = blockIdx.x;

    float acc[4][4][4];
    proj_body(Xs, Ws, X, TD, W, HID, TD, m0, n0, acc);

    const int t = threadIdx.x;
    const int w = t >> 5, lane = t & 31, g = lane >> 2, tig = lane & 3;
    const int mw = (w >> 1) * 64, nw = (w & 1) * 32;

#pragma unroll
    for (int mi = 0; mi < 4; mi++) {
        int r = m0 + mw + 16 * mi + g;
        int b_ = r >> 11, s_ = r & 2047;
        float* base0 = out + ((((size_t)(b_ * NH + h)) * SS + s_) << 6);
        float* base1 = base0 + (8 << 6);   // row + 8 (same b_, same tile)
#pragma unroll
        for (int nj = 0; nj < 4; nj++) {
            int col = nw + nj * 8 + 2 * tig;
            float2 bb = *(const float2*)&bias[n0 + col];
            *(float2*)&base0[col] = make_float2(acc[mi][nj][0] + bb.x, acc[mi][nj][1] + bb.y);
            *(float2*)&base1[col] = make_float2(acc[mi][nj][2] + bb.x, acc[mi][nj][3] + bb.y);
        }
    }
}

// ---------------------------------------------------------------------------
// Kernel 3: output projection  out = g_A @ Wo + bo
// ---------------------------------------------------------------------------
__global__ __launch_bounds__(128) void oproj_mma(
    const float* __restrict__ Wo, const float* __restrict__ bo,
    float* __restrict__ out)
{
    __shared__ float Xs[128 * 36];
    __shared__ float Ws[32 * 72];

    const int m0 = blockIdx.y * 128;
    const int n0 = blockIdx.x * 64;

    float acc[4][4][4];
    proj_body(Xs, Ws, g_A, HID, Wo, VD, HID, m0, n0, acc);

    const int t = threadIdx.x;
    const int w = t >> 5, lane = t & 31, g = lane >> 2, tig = lane & 3;
    const int mw = (w >> 1) * 64, nw = (w & 1) * 32;

#pragma unroll
    for (int mi = 0; mi < 4; mi++) {
        int r = m0 + mw + 16 * mi + g;
        float* base0 = out + (size_t)r * VD + n0;
        float* base1 = base0 + (size_t)8 * VD;
#pragma unroll
        for (int nj = 0; nj < 4; nj++) {
            int col = nw + nj * 8 + 2 * tig;
            float2 bb = *(const float2*)&bo[n0 + col];
            *(float2*)&base0[col] = make_float2(acc[mi][nj][0] + bb.x, acc[mi][nj][1] + bb.y);
            *(float2*)&base1[col] = make_float2(acc[mi][nj][2] + bb.x, acc[mi][nj][3] + bb.y);
        }
    }
}

// ===========================================================================
// Kernel 2: flash attention, mma.sync tf32, register softmax (FA-2 style).
// CTA: q-tile 128, 256 threads (8 warps), warp = 16 q rows. Key tile 64.
// Q frags preloaded in registers; S stays in C-fragments; P round-trips
// through smem within the owning warp only (__syncwarp, no CTA barrier).
// smem floats: Q[128][68] | K[64][68] | V[64][72] | P[128][68]
// ===========================================================================
#define AQ 0
#define AK 8704
#define AV 13056
#define AP 17664
#define ATTN_SMEM (26368 * 4)

__global__ __launch_bounds__(256, 1) void attn_mma()
{
    extern __shared__ float sm[];
    const int t = threadIdx.x;
    const int w = t >> 5, lane = t & 31, g = lane >> 2, tig = lane & 3;
    const int qt = blockIdx.x, bh = blockIdx.y;
    const int mrow = w * 16;

    const float* Qg = g_Q + (size_t)bh * SS * HD;
    const float* Kg = g_K + (size_t)bh * SS * HD;
    const float* Vg = g_V + (size_t)bh * SS * HD;

    // Load Q tile [128][64]
#pragma unroll
    for (int it = 0; it < 8; it++) {
        int i = t + it * 256;
        int r = i >> 4, fg = i & 15;
        float4 v = tf32r4(*(const float4*)&Qg[(size_t)(qt * 128 + r) * 64 + fg * 4]);
        *(float4*)&sm[AQ + r * 68 + fg * 4] = v;
    }
    __syncthreads();

    // Preload Q A-fragments (d = 8 k-steps)
    uint32_t qa[8][4];
#pragma unroll
    for (int ks = 0; ks < 8; ks++) {
        qa[ks][0] = __float_as_uint(sm[AQ + (mrow + g) * 68 + ks * 8 + tig]);
        qa[ks][1] = __float_as_uint(sm[AQ + (mrow + g + 8) * 68 + ks * 8 + tig]);
        qa[ks][2] = __float_as_uint(sm[AQ + (mrow + g) * 68 + ks * 8 + tig + 4]);
        qa[ks][3] = __float_as_uint(sm[AQ + (mrow + g + 8) * 68 + ks * 8 + tig + 4]);
    }

    float o[8][4];
#pragma unroll
    for (int nj = 0; nj < 8; nj++)
#pragma unroll
        for (int r = 0; r < 4; r++) o[nj][r] = 0.f;
    float m0 = -1e30f, m1 = -1e30f, l0 = 0.f, l1 = 0.f;

    for (int kt = 0; kt < 32; kt++) {
        __syncthreads();   // previous iteration's K/V reads complete
        // Load K,V tiles [64][64]
#pragma unroll
        for (int it = 0; it < 4; it++) {
            int i = t + it * 256;
            int r = i >> 4, fg = i & 15;
            float4 kv = tf32r4(*(const float4*)&Kg[(size_t)(kt * 64 + r) * 64 + fg * 4]);
            *(float4*)&sm[AK + r * 68 + fg * 4] = kv;
            float4 vv = tf32r4(*(const float4*)&Vg[(size_t)(kt * 64 + r) * 64 + fg * 4]);
            *(float4*)&sm[AV + r * 72 + fg * 4] = vv;
        }
        __syncthreads();

        // S = Q K^T  (16 q rows x 64 keys per warp)
        float s[8][4];
#pragma unroll
        for (int nj = 0; nj < 8; nj++)
#pragma unroll
            for (int r = 0; r < 4; r++) s[nj][r] = 0.f;

#pragma unroll
        for (int ks = 0; ks < 8; ks++)
#pragma unroll
            for (int nj = 0; nj < 8; nj++) {
                uint32_t b[2];
                b[0] = __float_as_uint(sm[AK + (nj * 8 + g) * 68 + ks * 8 + tig]);
                b[1] = __float_as_uint(sm[AK + (nj * 8 + g) * 68 + ks * 8 + tig + 4]);
                mma8(s[nj], qa[ks], b);
            }

        // Online softmax in registers (rows g and g+8; reduce across quad)
        float mx0 = m0, mx1 = m1;
#pragma unroll
        for (int nj = 0; nj < 8; nj++) {
            s[nj][0] *= 0.125f; s[nj][1] *= 0.125f;
            s[nj][2] *= 0.125f; s[nj][3] *= 0.125f;
            mx0 = fmaxf(mx0, fmaxf(s[nj][0], s[nj][1]));
            mx1 = fmaxf(mx1, fmaxf(s[nj][2], s[nj][3]));
        }
        mx0 = fmaxf(mx0, __shfl_xor_sync(0xffffffffu, mx0, 1));
        mx0 = fmaxf(mx0, __shfl_xor_sync(0xffffffffu, mx0, 2));
        mx1 = fmaxf(mx1, __shfl_xor_sync(0xffffffffu, mx1, 1));
        mx1 = fmaxf(mx1, __shfl_xor_sync(0xffffffffu, mx1, 2));

        float corr0 = __expf(m0 - mx0), corr1 = __expf(m1 - mx1);
        float ls0 = 0.f, ls1 = 0.f;
#pragma unroll
        for (int nj = 0; nj < 8; nj++) {
            float p0 = __expf(s[nj][0] - mx0);
            float p1 = __expf(s[nj][1] - mx0);
            float p2 = __expf(s[nj][2] - mx1);
            float p3 = __expf(s[nj][3] - mx1);
            ls0 += p0 + p1;
            ls1 += p2 + p3;
            *(float2*)&sm[AP + (mrow + g) * 68 + nj * 8 + 2 * tig] =
                make_float2(tf32r(p0), tf32r(p1));
            *(float2*)&sm[AP + (mrow + g + 8) * 68 + nj * 8 + 2 * tig] =
                make_float2(tf32r(p2), tf32r(p3));
        }
        ls0 += __shfl_xor_sync(0xffffffffu, ls0, 1);
        ls0 += __shfl_xor_sync(0xffffffffu, ls0, 2);
        ls1 += __shfl_xor_sync(0xffffffffu, ls1, 1);
        ls1 += __shfl_xor_sync(0xffffffffu, ls1, 2);
        l0 = l0 * corr0 + ls0;
        l1 = l1 * corr1 + ls1;
        m0 = mx0; m1 = mx1;

#pragma unroll
        for (int nj = 0; nj < 8; nj++) {
            o[nj][0] *= corr0; o[nj][1] *= corr0;
            o[nj][2] *= corr1; o[nj][3] *= corr1;
        }
        __syncwarp();   // P rows are warp-private; only intra-warp visibility needed

        // O += P V   (key dim = 8 k-steps of 8)
#pragma unroll
        for (int ks = 0; ks < 8; ks++) {
            uint32_t pa[4];
            pa[0] = __float_as_uint(sm[AP + (mrow + g) * 68 + ks * 8 + tig]);
            pa[1] = __float_as_uint(sm[AP + (mrow + g + 8) * 68 + ks * 8 + tig]);
            pa[2] = __float_as_uint(sm[AP + (mrow + g) * 68 + ks * 8 + tig + 4]);
            pa[3] = __float_as_uint(sm[AP + (mrow + g + 8) * 68 + ks * 8 + tig + 4]);
#pragma unroll
            for (int nj = 0; nj < 8; nj++) {
                uint32_t b[2];
                b[0] = __float_as_uint(sm[AV + (ks * 8 + tig) * 72 + nj * 8 + g]);
                b[1] = __float_as_uint(sm[AV + (ks * 8 + tig + 4) * 72 + nj * 8 + g]);
                mma8(o[nj], pa, b);
            }
        }
    }

    // Epilogue: normalize and write to g_A [b*s][h*64]
    const float inv0 = 1.f / l0, inv1 = 1.f / l1;
    const int b_ = bh >> 3, h = bh & 7;
    const int r0 = qt * 128 + mrow + g;
    float* p0 = g_A + ((size_t)(b_ * SS + r0)) * HID + h * 64;
    float* p1 = p0 + (size_t)8 * HID;
#pragma unroll
    for (int nj = 0; nj < 8; nj++) {
        *(float2*)&p0[nj * 8 + 2 * tig] = make_float2(o[nj][0] * inv0, o[nj][1] * inv0);
        *(float2*)&p1[nj * 8 + 2 * tig] = make_float2(o[nj][2] * inv1, o[nj][3] * inv1);
    }
}

// ===========================================================================
extern "C" void kernel_launch(void* const* d_in, const int* in_sizes, int n_in,
                              void* d_out, int out_size)
{
    const float* X  = (const float*)d_in[0];
    const float* Wq = (const float*)d_in[1];
    const float* bq = (const float*)d_in[2];
    const float* Wk = (const float*)d_in[3];
    const float* bk = (const float*)d_in[4];
    const float* Wv = (const float*)d_in[5];
    const float* bv = (const float*)d_in[6];
    const float* Wo = (const float*)d_in[7];
    const float* bo = (const float*)d_in[8];
    float* out = (float*)d_out;

    cudaFuncSetAttribute(attn_mma, cudaFuncAttributeMaxDynamicSharedMemorySize, ATTN_SMEM);

    qkv_mma<<<dim3(HID / 64, MM / 128, 3), 128>>>(X, Wq, bq, Wk, bk, Wv, bv);
    attn_mma<<<dim3(SS / 128, NB * NH), 256, ATTN_SMEM>>>();
    oproj_mma<<<dim3(VD / 64, MM / 128), 128>>>(Wo, bo, out);
}